// round 1
// baseline (speedup 1.0000x reference)
#include <cuda_runtime.h>

#define BB 2
#define CC 64
#define DD 48
#define HH 48
#define WW 48
#define HW (HH*WW)          // 2304
#define DHW (DD*HW)         // 110592
#define TOT (BB*CC*DHW)     // 14155776

// Scratch (static device globals; no allocation allowed in kernel_launch)
__device__ float g_t1[TOT];
__device__ float g_t2[TOT];

// ---------------------------------------------------------------------------
// Kernel 1: depthwise 5x5x5, pad 2.  x -> g_t1
// Block: (zt, yt, b*c). Tile: 4z x 16y x 48w outputs.
// Threads: 128 = 8 w-groups (6 w each) x 16 y. Each thread: 4z x 6w outputs.
// Smem tile: 8z x 20y x 52w input (zero-padded halo).
// ---------------------------------------------------------------------------
__global__ __launch_bounds__(128) void dw5_kernel(
    const float* __restrict__ x,
    const float* __restrict__ w0,
    const float* __restrict__ b0)
{
    __shared__ float sh[8 * 20 * 52];
    __shared__ float sw[128];

    const int zt  = blockIdx.x;          // 0..11
    const int yt  = blockIdx.y;          // 0..2
    const int bc  = blockIdx.z;          // 0..127
    const int c   = bc & 63;
    const int tid = threadIdx.x;
    const int z0  = zt * 4;
    const int y0  = yt * 16;

    const float* __restrict__ xin = x + (size_t)bc * DHW;

    if (tid < 125) sw[tid] = w0[c * 125 + tid];

    // Load input tile with zero padding
    for (int idx = tid; idx < 8 * 20 * 52; idx += 128) {
        int zi = idx / (20 * 52);
        int r  = idx % (20 * 52);
        int yi = r / 52;
        int wi = r % 52;
        int gz = z0 - 2 + zi;
        int gy = y0 - 2 + yi;
        int gw = wi - 2;
        float v = 0.0f;
        if ((unsigned)gz < 48u && (unsigned)gy < 48u && (unsigned)gw < 48u)
            v = xin[gz * HW + gy * WW + gw];
        sh[idx] = v;
    }
    __syncthreads();

    const int wg    = tid & 7;
    const int ty    = tid >> 3;
    const int wbase = wg * 6;

    float acc[4][6];
    #pragma unroll
    for (int i = 0; i < 4; ++i)
        #pragma unroll
        for (int k = 0; k < 6; ++k) acc[i][k] = 0.0f;

    // zi: input layer in tile (global z = z0-2+zi); contributes to oz = zi-dz
    #pragma unroll
    for (int zi = 0; zi < 8; ++zi) {
        #pragma unroll 1
        for (int dy = 0; dy < 5; ++dy) {
            const float* __restrict__ row = &sh[(zi * 20 + ty + dy) * 52 + wbase];
            float v[10];
            #pragma unroll
            for (int j = 0; j < 10; ++j) v[j] = row[j];
            #pragma unroll
            for (int dz = 0; dz < 5; ++dz) {
                const int oz = zi - dz;
                if (oz < 0 || oz > 3) continue;   // compile-time (zi, dz unrolled)
                const float* __restrict__ wr = &sw[(dz * 5 + dy) * 5];
                #pragma unroll
                for (int dw = 0; dw < 5; ++dw) {
                    const float wv = wr[dw];
                    #pragma unroll
                    for (int k = 0; k < 6; ++k)
                        acc[oz][k] += wv * v[k + dw];
                }
            }
        }
    }

    const float bias = __ldg(&b0[c]);
    float* __restrict__ obase = g_t1 + (size_t)bc * DHW;
    #pragma unroll
    for (int oz = 0; oz < 4; ++oz) {
        float* __restrict__ op = obase + (z0 + oz) * HW + (y0 + ty) * WW + wbase;
        #pragma unroll
        for (int k = 0; k < 6; ++k) op[k] = acc[oz][k] + bias;
    }
}

// ---------------------------------------------------------------------------
// Kernel 2: depthwise 7x7x7, dilation 3, pad 9.  g_t1 -> g_t2
// Residue decomposition: for residue r=(rz,ry,rw) in {0,1,2}^3, the dilated
// conv is a dense 7^3 pad-3 conv on the 16^3 subgrid x[3q+r].
// Block: (res*2+zhalf, c, b). Tile: 8z x 16y x 16w subgrid outputs.
// Threads: 128 = 2 w-groups (8 w) x 16 y x 4 z-groups (2 z). 16 outputs/thread.
// Smem tile: 14 x 22 x 22 subgrid input (zero-padded halo of 3).
// ---------------------------------------------------------------------------
__global__ __launch_bounds__(128) void dw7_kernel(
    const float* __restrict__ ws,
    const float* __restrict__ bs)
{
    __shared__ float sh[14 * 22 * 22];
    __shared__ float sw[344];

    const int bx    = blockIdx.x;        // 0..53
    const int zhalf = bx & 1;
    const int res   = bx >> 1;           // 0..26
    const int rz = res / 9, ry = (res / 3) % 3, rw = res % 3;
    const int c  = blockIdx.y;
    const int b  = blockIdx.z;
    const int bc = b * 64 + c;
    const int tid = threadIdx.x;

    const float* __restrict__ xin = g_t1 + (size_t)bc * DHW;

    for (int i = tid; i < 343; i += 128) sw[i] = ws[c * 343 + i];

    const int z0sub = zhalf * 8;
    for (int idx = tid; idx < 14 * 22 * 22; idx += 128) {
        int zi = idx / 484;
        int r  = idx % 484;
        int yi = r / 22;
        int wi = r % 22;
        int sz = z0sub - 3 + zi;
        int sy = yi - 3;
        int sx = wi - 3;
        float v = 0.0f;
        if ((unsigned)sz < 16u && (unsigned)sy < 16u && (unsigned)sx < 16u)
            v = xin[(3 * sz + rz) * HW + (3 * sy + ry) * WW + (3 * sx + rw)];
        sh[idx] = v;
    }
    __syncthreads();

    const int wg    = tid & 1;
    const int ty    = (tid >> 1) & 15;
    const int zg    = tid >> 5;          // 0..3
    const int wbase = wg * 8;
    const int ozb   = zg * 2;

    float acc[2][8];
    #pragma unroll
    for (int i = 0; i < 2; ++i)
        #pragma unroll
        for (int k = 0; k < 8; ++k) acc[i][k] = 0.0f;

    // tile layer t = ozb + s; output oz_block = ozb + loz uses t = ozb+loz+dz
    #pragma unroll
    for (int s = 0; s < 8; ++s) {
        const int t = ozb + s;
        #pragma unroll 1
        for (int dy = 0; dy < 7; ++dy) {
            const float* __restrict__ row = &sh[(t * 22 + ty + dy) * 22 + wbase];
            float v[14];
            #pragma unroll
            for (int j = 0; j < 14; ++j) v[j] = row[j];
            if (s <= 6) {                 // loz = 0, dz = s
                const float* __restrict__ wr = &sw[(s * 7 + dy) * 7];
                #pragma unroll
                for (int dw = 0; dw < 7; ++dw) {
                    const float wv = wr[dw];
                    #pragma unroll
                    for (int k = 0; k < 8; ++k)
                        acc[0][k] += wv * v[k + dw];
                }
            }
            if (s >= 1) {                 // loz = 1, dz = s-1
                const float* __restrict__ wr = &sw[((s - 1) * 7 + dy) * 7];
                #pragma unroll
                for (int dw = 0; dw < 7; ++dw) {
                    const float wv = wr[dw];
                    #pragma unroll
                    for (int k = 0; k < 8; ++k)
                        acc[1][k] += wv * v[k + dw];
                }
            }
        }
    }

    const float bias = __ldg(&bs[c]);
    float* __restrict__ obase = g_t2 + (size_t)bc * DHW;
    #pragma unroll
    for (int loz = 0; loz < 2; ++loz) {
        const int sz = z0sub + ozb + loz;     // 0..15
        const int gz = 3 * sz + rz;
        const int gy = 3 * ty + ry;
        float* __restrict__ op = obase + gz * HW + gy * WW + rw;
        #pragma unroll
        for (int k = 0; k < 8; ++k)
            op[3 * (wbase + k)] = acc[loz][k] + bias;
    }
}

// ---------------------------------------------------------------------------
// Kernel 3: pointwise 64x64 conv + bias + gate by x.  g_t2, x -> out
// Block: 128 spatial points x all 64 out-channels. Threads 256 = 32 pg x 8 cg.
// Each thread: 8 co x 4 p outputs. W1 staged in smem (broadcast reads);
// t2 tile read as float4 LDG (8x L1 reuse within block).
// ---------------------------------------------------------------------------
__global__ __launch_bounds__(256) void pw_kernel(
    const float* __restrict__ x,
    const float* __restrict__ w1,
    const float* __restrict__ b1,
    float* __restrict__ out)
{
    __shared__ float sW[64 * 64];

    const int p0  = blockIdx.x * 128;
    const int b   = blockIdx.y;
    const int tid = threadIdx.x;

    for (int i = tid; i < 4096; i += 256) sW[i] = w1[i];
    __syncthreads();

    const int pg = tid & 31;     // 32 groups of 4 points
    const int cg = tid >> 5;     // 8 groups of 8 out-channels

    float acc[8][4];
    #pragma unroll
    for (int j = 0; j < 8; ++j)
        #pragma unroll
        for (int k = 0; k < 4; ++k) acc[j][k] = 0.0f;

    const float4* __restrict__ tp =
        (const float4*)(g_t2 + (size_t)b * 64 * DHW + p0) + pg;

    #pragma unroll 4
    for (int ci = 0; ci < 64; ++ci) {
        const float4 v = __ldg(tp + (size_t)ci * (DHW / 4));
        const float* __restrict__ wr = &sW[ci];   // sW[co*64+ci], broadcast per warp
        #pragma unroll
        for (int j = 0; j < 8; ++j) {
            const float wv = wr[(cg * 8 + j) * 64];
            acc[j][0] += wv * v.x;
            acc[j][1] += wv * v.y;
            acc[j][2] += wv * v.z;
            acc[j][3] += wv * v.w;
        }
    }

    #pragma unroll
    for (int j = 0; j < 8; ++j) {
        const int co = cg * 8 + j;
        const float bias = __ldg(&b1[co]);
        const size_t off = (size_t)(b * 64 + co) * DHW + p0 + pg * 4;
        const float4 xv = __ldg((const float4*)(x + off));
        float4 ov;
        ov.x = xv.x * (acc[j][0] + bias);
        ov.y = xv.y * (acc[j][1] + bias);
        ov.z = xv.z * (acc[j][2] + bias);
        ov.w = xv.w * (acc[j][3] + bias);
        *(float4*)(out + off) = ov;
    }
}

// ---------------------------------------------------------------------------
extern "C" void kernel_launch(void* const* d_in, const int* in_sizes, int n_in,
                              void* d_out, int out_size)
{
    const float* x  = (const float*)d_in[0];
    const float* w0 = (const float*)d_in[1];
    const float* b0 = (const float*)d_in[2];
    const float* ws = (const float*)d_in[3];
    const float* bs = (const float*)d_in[4];
    const float* w1 = (const float*)d_in[5];
    const float* b1 = (const float*)d_in[6];
    float* out = (float*)d_out;

    dw5_kernel<<<dim3(12, 3, BB * CC), 128>>>(x, w0, b0);
    dw7_kernel<<<dim3(54, CC, BB), 128>>>(ws, bs);
    pw_kernel<<<dim3(DHW / 128, BB), 256>>>(x, w1, b1, out);
}